// round 12
// baseline (speedup 1.0000x reference)
#include <cuda_runtime.h>
#include <cstdint>

// CondConv2d via fp16 mma.sync.m16n8k16 implicit GEMM (f32 accumulate).
// R12: 3 CTAs/SM (24 warps). Warp = 1h x 32px x 32co (32 acc regs);
// CTA = 4h x 64w tile, 2 tiles per CTA, R11 prefetch pipeline.

#define B_    16
#define CIN_  32
#define HW_   256
#define COUT_ 32
#define NEXP  8
#define NPARAM 9216

// ---- smem layout in 4-byte units ----
#define RAWP   72                 // raw f32 pitch
#define XROWS  6                  // h0-1 .. h0+4
#define SCR_U  0                  // 16 planes x 6 rows x 72 = 6912 words
#define XPH    76                 // jpair stride 456 % 32 == 8 -> banks distinct
#define XSH_U  6912               // 8 jpairs x 6 rows x 76 = 3648 words
#define WS_U   10560              // 2 halves x 2304 words (k16 fragment order)
#define BIAS_U 15168
#define SMEM_U 15200
#define SMEM_BYTES (SMEM_U * 4)   // 60800 B -> 3 CTA/SM

__device__ uint32_t g_wt_h[B_ * 4608];   // [b][cc][t][mt][lane][w] f16x2 words
__device__ float    g_bias[B_ * COUT_];

__device__ __forceinline__ uint32_t smem_u32(const void* p) {
    uint32_t a;
    asm("{ .reg .u64 t; cvta.to.shared.u64 t, %1; cvt.u32.u64 %0, t; }" : "=r"(a) : "l"(p));
    return a;
}
__device__ __forceinline__ uint32_t pack_f16x2(float hi, float lo) {
    uint32_t d;
    asm("cvt.rn.f16x2.f32 %0, %1, %2;" : "=r"(d) : "f"(hi), "f"(lo));
    return d;
}
__device__ __forceinline__ void mma_f16(float c[4], const uint32_t a[4],
                                        uint32_t b0, uint32_t b1) {
    asm volatile(
        "mma.sync.aligned.m16n8k16.row.col.f32.f16.f16.f32 "
        "{%0,%1,%2,%3}, {%4,%5,%6,%7}, {%8,%9}, {%0,%1,%2,%3};"
        : "+f"(c[0]), "+f"(c[1]), "+f"(c[2]), "+f"(c[3])
        : "r"(a[0]), "r"(a[1]), "r"(a[2]), "r"(a[3]), "r"(b0), "r"(b1));
}
__device__ __forceinline__ void cp_async4(uint32_t dst, const void* src, uint32_t sz) {
    asm volatile("cp.async.ca.shared.global [%0], [%1], 4, %2;"
                 :: "r"(dst), "l"(src), "r"(sz) : "memory");
}
__device__ __forceinline__ void cp_async16(uint32_t dst, const void* src) {
    asm volatile("cp.async.cg.shared.global [%0], [%1], 16;"
                 :: "r"(dst), "l"(src) : "memory");
}
__device__ __forceinline__ void cp_async16z(uint32_t dst, const void* src, uint32_t sz) {
    asm volatile("cp.async.cg.shared.global [%0], [%1], 16, %2;"
                 :: "r"(dst), "l"(src), "r"(sz) : "memory");
}
#define CP_COMMIT() asm volatile("cp.async.commit_group;" ::: "memory")
#define CP_WAIT0()  asm volatile("cp.async.wait_group 0;" ::: "memory")

// ---------------------------------------------------------------------------
// Kernel 1: mix experts -> fragment-ordered fp16 weights + bias (unchanged).
// ---------------------------------------------------------------------------
__global__ void condconv_prep_kernel(const float* __restrict__ rw,
                                     const float* __restrict__ ew,
                                     const float* __restrict__ eb) {
    int b = blockIdx.x, cc = blockIdx.y;
    int tid = threadIdx.x;
    float r[NEXP];
#pragma unroll
    for (int e = 0; e < NEXP; e++) r[e] = rw[b * NEXP + e];

    for (int i = tid; i < 2304; i += 256) {
        int t    = i >> 8;
        int r2   = i & 255;
        int mt   = r2 >> 7;
        int lane = (r2 >> 2) & 31;
        int w    = r2 & 3;
        int g = lane >> 2, tig = lane & 3;
        int co = mt * 16 + g + (w & 1) * 8;
        int ci = cc * 16 + 2 * tig + (w >> 1) * 8;
        int src = co * (CIN_ * 9) + ci * 9 + t;
        float s_lo = 0.f, s_hi = 0.f;
#pragma unroll
        for (int e = 0; e < NEXP; e++) {
            s_lo += r[e] * ew[e * NPARAM + src];
            s_hi += r[e] * ew[e * NPARAM + src + 9];
        }
        g_wt_h[(b * 2 + cc) * 2304 + i] = pack_f16x2(s_hi, s_lo);
    }
    if (cc == 0 && tid < COUT_) {
        float s = 0.f;
#pragma unroll
        for (int e = 0; e < NEXP; e++) s += r[e] * eb[e * COUT_ + tid];
        g_bias[b * COUT_ + tid] = s;
    }
}

// ---------------------------------------------------------------------------
// stage 16 planes of one (tile, half) job into scr as raw f32.
// ---------------------------------------------------------------------------
__device__ __forceinline__ void stage_raw(uint32_t scr, const float* __restrict__ xq,
                                          int h0, int w0, int tid) {
    for (int i = tid; i < 1536; i += 256) {            // interior 16B
        int v    = i & 15;
        int rest = i >> 4;
        int pl   = rest / XROWS;
        int row  = rest - pl * XROWS;
        int ih   = h0 - 1 + row;
        bool ok = (unsigned)ih < 256u;
        const float* src = xq + (size_t)pl * (HW_ * HW_) + (ok ? ih * HW_ : 0) + w0 + 4 * v;
        cp_async16z(scr + (uint32_t)(pl * (XROWS * RAWP) + row * RAWP + 4 + 4 * v) * 4,
                    src, ok ? 16u : 0u);
    }
    for (int i = tid; i < 192; i += 256) {             // halo scalars
        int side = i & 1;
        int rest = i >> 1;
        int pl   = rest / XROWS;
        int row  = rest - pl * XROWS;
        int ih = h0 - 1 + row;
        int iw = side ? (w0 + 64) : (w0 - 1);
        bool ok = ((unsigned)ih < 256u) && ((unsigned)iw < 256u);
        const float* src = xq + (size_t)pl * (HW_ * HW_) + (ok ? (ih * HW_ + iw) : 0);
        cp_async4(scr + (uint32_t)(pl * (XROWS * RAWP) + row * RAWP + (side ? 68 : 3)) * 4,
                  src, ok ? 4u : 0u);
    }
}

// convert scr f32 (16 planes) -> xsh packed f16x2 over adjacent planes
__device__ __forceinline__ void convert_half(const float* scr, uint32_t* xsh, int tid) {
    for (int i = tid; i < 1680; i += 256) {
        int j   = i / 210;
        int r1  = i - j * 210;
        int row = r1 / 35;
        int p2  = r1 - row * 35;
        const float* s0 = scr + (2 * j)     * (XROWS * RAWP) + row * RAWP + 2 * p2;
        const float* s1 = scr + (2 * j + 1) * (XROWS * RAWP) + row * RAWP + 2 * p2;
        float2 f0 = *(const float2*)s0;
        float2 f1 = *(const float2*)s1;
        uint2 o;
        o.x = pack_f16x2(f1.x, f0.x);
        o.y = pack_f16x2(f1.y, f0.y);
        *(uint2*)(xsh + j * (XROWS * XPH) + row * XPH + 2 * p2) = o;
    }
}

// compute one 16-ci half; warp covers 1 output row (wy), 32 px (wh half).
__device__ __forceinline__ void compute_half(const uint32_t* xsh, const uint32_t* ws,
                                             float acc[2][4][4],
                                             int lane, int g, int tig, int wy, int wh) {
    const uint4* wf = (const uint4*)ws + lane;
    const uint32_t* xf = xsh + wy * XPH + wh * 32 + g + 3 + tig * (XROWS * XPH);

#pragma unroll
    for (int kw = 0; kw < 3; kw++) {
        uint32_t B0[3][4], B1[3][4];
#pragma unroll
        for (int xr = 0; xr < 3; xr++) {
            const uint32_t* xt = xf + xr * XPH + kw;
#pragma unroll
            for (int nt = 0; nt < 4; nt++) {
                B0[xr][nt] = xt[nt * 8];
                B1[xr][nt] = xt[nt * 8 + 4 * (XROWS * XPH)];
            }
        }
#pragma unroll
        for (int kh = 0; kh < 3; kh++) {
            const int t = kh * 3 + kw;
            uint4 q0 = wf[(t * 2) * 32];
            uint4 q1 = wf[(t * 2 + 1) * 32];
            uint32_t a0[4] = {q0.x, q0.y, q0.z, q0.w};
            uint32_t a1[4] = {q1.x, q1.y, q1.z, q1.w};
#pragma unroll
            for (int nt = 0; nt < 4; nt++) {
                mma_f16(acc[0][nt], a0, B0[kh][nt], B1[kh][nt]);
                mma_f16(acc[1][nt], a1, B0[kh][nt], B1[kh][nt]);
            }
        }
    }
}

__device__ __forceinline__ void store_tile(float acc[2][4][4], float* __restrict__ out,
                                           const float* bs, int b, int oh0, int w0,
                                           int g, int tig, int wy, int wh) {
    const int oh = oh0 + wy;
#pragma unroll
    for (int mt = 0; mt < 2; mt++) {
#pragma unroll
        for (int nt = 0; nt < 4; nt++) {
            int co = mt * 16 + g;
            int pw = w0 + wh * 32 + nt * 8 + 2 * tig;
            float2 v0, v1;
            v0.x = acc[mt][nt][0] + bs[co];
            v0.y = acc[mt][nt][1] + bs[co];
            v1.x = acc[mt][nt][2] + bs[co + 8];
            v1.y = acc[mt][nt][3] + bs[co + 8];
            *(float2*)&out[(((size_t)b * COUT_ + co)     * HW_ + oh) * HW_ + pw] = v0;
            *(float2*)&out[(((size_t)b * COUT_ + co + 8) * HW_ + oh) * HW_ + pw] = v1;
        }
    }
}

// ---------------------------------------------------------------------------
// Kernel 2: conv. Grid (4, 32, 16); 256 threads, 8 warps; 2 x 4h tiles per CTA.
// jobs j=0..3: tile = j>>1 (h0 = hb + 4*tile), half = j&1.
// ---------------------------------------------------------------------------
__global__ __launch_bounds__(256, 3)
void condconv_mma_kernel(const float* __restrict__ x, float* __restrict__ out) {
    extern __shared__ float sm[];
    const uint32_t sbase = smem_u32(sm);

    const int b  = blockIdx.z;
    const int hb = blockIdx.y * 8;       // 2-tile strip base row
    const int w0 = blockIdx.x * 64;
    const int tid = threadIdx.x;
    const int lane = tid & 31, wid = tid >> 5;
    const int g = lane >> 2, tig = lane & 3;
    const int wy = wid >> 1, wh = wid & 1;   // row 0..3, w-half

    const uint32_t* gw = g_wt_h + b * 4608;
    const float* xb = x + (size_t)b * CIN_ * HW_ * HW_;
    uint32_t* xsh = (uint32_t*)(sm + XSH_U);
    const uint32_t* ws = (const uint32_t*)(sm + WS_U);
    const uint32_t scr_a = sbase + SCR_U * 4;

    if (tid < COUT_) sm[BIAS_U + tid] = g_bias[b * COUT_ + tid];

    // prologue: weights (both halves) + raw job0 in one cp.async group
    for (int i = tid; i < 1152; i += 256)
        cp_async16(sbase + (WS_U + i * 4) * 4, gw + i * 4);
    stage_raw(scr_a, xb, hb, w0, tid);
    CP_COMMIT();

    float acc[2][4][4];
#pragma unroll
    for (int mt = 0; mt < 2; mt++)
#pragma unroll
        for (int nt = 0; nt < 4; nt++)
#pragma unroll
            for (int i = 0; i < 4; i++) acc[mt][nt][i] = 0.f;

#pragma unroll 1
    for (int j = 0; j < 4; j++) {
        CP_WAIT0();
        __syncthreads();                 // raw(j) visible; xsh free
        convert_half(sm + SCR_U, xsh, tid);
        __syncthreads();                 // xsh ready; scr free

        if (j < 3) {                     // prefetch raw(j+1) under compute(j)
            int nj = j + 1;
            stage_raw(scr_a, xb + (size_t)((nj & 1) * 16) * (HW_ * HW_),
                      hb + (nj >> 1) * 4, w0, tid);
            CP_COMMIT();
        }

        compute_half(xsh, ws + (j & 1) * 2304, acc, lane, g, tig, wy, wh);

        if (j == 1) {                    // tile 0 done
            store_tile(acc, out, sm + BIAS_U, b, hb, w0, g, tig, wy, wh);
#pragma unroll
            for (int mt = 0; mt < 2; mt++)
#pragma unroll
                for (int nt = 0; nt < 4; nt++)
#pragma unroll
                    for (int i = 0; i < 4; i++) acc[mt][nt][i] = 0.f;
        }
    }

    store_tile(acc, out, sm + BIAS_U, b, hb + 4, w0, g, tig, wy, wh);
}

// ---------------------------------------------------------------------------
extern "C" void kernel_launch(void* const* d_in, const int* in_sizes, int n_in,
                              void* d_out, int out_size) {
    const float* x  = (const float*)d_in[0];
    const float* rw = (const float*)d_in[1];
    const float* ew = (const float*)d_in[2];
    const float* eb = (const float*)d_in[3];
    float* out = (float*)d_out;

    condconv_prep_kernel<<<dim3(B_, 2), 256>>>(rw, ew, eb);

    cudaFuncSetAttribute(condconv_mma_kernel,
                         cudaFuncAttributeMaxDynamicSharedMemorySize, SMEM_BYTES);
    dim3 grid(HW_ / 64, HW_ / 8, B_);
    condconv_mma_kernel<<<grid, 256, SMEM_BYTES>>>(x, out);
}